// round 15
// baseline (speedup 1.0000x reference)
#include <cuda_runtime.h>
#include <math.h>

#define IMN 4096
#define NPIX (IMN*IMN)
#define MED_RANK 8388607u   /* (NPIX-1)/2 */

typedef unsigned long long u64;

// ---------------- packed f32x2 helpers (Blackwell) ----------------
__device__ __forceinline__ u64 pk2(float lo, float hi) {
    u64 d; asm("mov.b64 %0, {%1, %2};" : "=l"(d) : "f"(lo), "f"(hi)); return d;
}
__device__ __forceinline__ void upk2(u64 v, float& lo, float& hi) {
    asm("mov.b64 {%0, %1}, %2;" : "=f"(lo), "=f"(hi) : "l"(v));
}
__device__ __forceinline__ u64 mul2(u64 a, u64 b) {
    u64 d; asm("mul.rn.f32x2 %0, %1, %2;" : "=l"(d) : "l"(a), "l"(b)); return d;
}
__device__ __forceinline__ u64 fma2(u64 a, u64 b, u64 c) {
    u64 d; asm("fma.rn.f32x2 %0, %1, %2, %3;" : "=l"(d) : "l"(a), "l"(b), "l"(c)); return d;
}

// ---------------- device scratch (no allocations allowed) ----------------
__device__ float    g_R[NPIX];            // Harris response
__device__ unsigned g_hist12[8 * 4096];   // pass-1 hist, 8 replicas (top 12 bits)
__device__ unsigned g_hist20[1 << 20];    // pass-2 histogram (low 20 bits)
__device__ unsigned g_chunk[1024];        // chunk sums for 20-bit select
__device__ unsigned g_prefix;             // selected top-12-bit bin
__device__ unsigned g_rank;               // remaining rank
__device__ float    g_med;                // selected median value

// monotonic float<->uint order transform
__device__ __forceinline__ unsigned f2u(float f) {
    unsigned u = __float_as_uint(f);
    return (u & 0x80000000u) ? ~u : (u | 0x80000000u);
}
__device__ __forceinline__ float u2f(unsigned u) {
    return (u & 0x80000000u) ? __uint_as_float(u & 0x7fffffffu)
                             : __uint_as_float(~u);
}

// ---------------- fused Sobel + products + 7x7 Gaussian -> R + 12-bit hist --
// 32x32 output tile, halo 4. 256 threads, 6 blocks/SM. 4096-bin histogram
// overlaid on dead sx/sIxy smem; warp-aggregated (match_any) updates kill
// same-address ATOMS serialization; global merge skip-zero + 8 replicas.
// Per-output FP op sequence identical to round-8..14 => bit-exact R.
__global__ __launch_bounds__(256, 6) void k_R(const float* __restrict__ x,
                                              const float* __restrict__ gk) {
    __shared__ union {
        struct {
            float sx  [40][45];   // cols 40..44 padding (garbage ok)
            u64   sIxy[38][43];   // packed (Ix,Iy); cols 38..42 padding
        } s;
        unsigned hist[4096];      // overlays sx/sIxy after stage 2
    } u_;
    __shared__ u64   sh01[38][33];    // packed (blur(Ix^2), blur(Iy^2))
    __shared__ float sh2 [38][33];    // blur(Ix*Iy)

    const int tid = threadIdx.x;
    const int bx = blockIdx.x * 32, by = blockIdx.y * 32;
    const bool interior = (blockIdx.x != 0) & (blockIdx.x != 127) &
                          (blockIdx.y != 0) & (blockIdx.y != 127);

    // 1D gaussian factors from provided 2D kernel: w[k] = g2[3][k]/sqrt(g2[3][3])
    float winv = rsqrtf(gk[24]);
    float w[7]; u64 w2[7];
#pragma unroll
    for (int k = 0; k < 7; k++) { w[k] = gk[21 + k] * winv; w2[k] = pk2(w[k], w[k]); }

    // stage 0: load x tile (interior: unguarded)
    if (interior) {
        const float* xb = x + (by - 4) * IMN + (bx - 4);
#pragma unroll
        for (int i = tid; i < 40 * 40; i += 256) {
            int r = i / 40, c = i % 40;
            u_.s.sx[r][c] = xb[r * IMN + c];
        }
    } else {
        for (int i = tid; i < 40 * 40; i += 256) {
            int r = i / 40, c = i % 40;
            int gy = by - 4 + r, gx = bx - 4 + c;
            float v = 0.0f;
            if ((unsigned)gy < IMN && (unsigned)gx < IMN) v = x[gy * IMN + gx];
            u_.s.sx[r][c] = v;
        }
    }
    __syncthreads();

    // stage 1: Sobel; 7 consecutive cols per task (38 rows x 6 groups = 228 tasks)
    if (tid < 228) {
        int r  = tid % 38;
        int cb = (tid / 38) * 7;          // 0,7,...,35
        float r0[9], r1[9], r2[9];
#pragma unroll
        for (int j = 0; j < 9; j++) {     // unguarded: sx padded to 45 cols
            r0[j] = u_.s.sx[r    ][cb + j];
            r1[j] = u_.s.sx[r + 1][cb + j];
            r2[j] = u_.s.sx[r + 2][cb + j];
        }
        if (interior) {
#pragma unroll
            for (int j = 0; j < 7; j++) {
                int c = cb + j;
                if (c < 38) {
                    float ix = (r0[j+2] - r0[j]) + 2.0f*(r1[j+2] - r1[j]) + (r2[j+2] - r2[j]);
                    float iy = (r2[j] + 2.0f*r2[j+1] + r2[j+2]) - (r0[j] + 2.0f*r0[j+1] + r0[j+2]);
                    u_.s.sIxy[r][c] = pk2(ix, iy);
                }
            }
        } else {
            int gy = by - 3 + r;
            bool rowok = (unsigned)gy < IMN;
#pragma unroll
            for (int j = 0; j < 7; j++) {
                int c = cb + j;
                if (c < 38) {
                    float ix = 0.0f, iy = 0.0f;
                    int gx = bx - 3 + c;
                    if (rowok && (unsigned)gx < IMN) {
                        ix = (r0[j+2] - r0[j]) + 2.0f*(r1[j+2] - r1[j]) + (r2[j+2] - r2[j]);
                        iy = (r2[j] + 2.0f*r2[j+1] + r2[j+2]) - (r0[j] + 2.0f*r0[j+1] + r0[j+2]);
                    }
                    u_.s.sIxy[r][c] = pk2(ix, iy);
                }
            }
        }
    }
    __syncthreads();

    // stage 2: horizontal 7-tap gaussian; 6 cols per task (38 x 6 = 228 tasks)
    if (tid < 228) {
        int r  = tid % 38;
        int cb = (tid / 38) * 6;          // 0,6,...,30
        u64 p01[12]; float p2[12];
#pragma unroll
        for (int i = 0; i < 12; i++) {    // unguarded: sIxy padded to 43 cols;
            u64 dp = u_.s.sIxy[r][cb + i]; // garbage only feeds skipped outputs
            float ax, ay; upk2(dp, ax, ay);
            p01[i] = mul2(dp, dp);        // (Ix*Ix, Iy*Iy), rn each lane
            p2[i]  = ax * ay;
        }
#pragma unroll
        for (int j = 0; j < 6; j++) {
            int c = cb + j;
            if (c < 32) {
                u64 a01 = pk2(0.0f, 0.0f);
                float a2 = 0.0f;
#pragma unroll
                for (int k = 0; k < 7; k++) {
                    a01 = fma2(w2[k], p01[j + k], a01);
                    a2  = fmaf(w[k], p2[j + k], a2);
                }
                sh01[r][c] = a01;
                sh2 [r][c] = a2;
            }
        }
    }
    __syncthreads();   // sx/sIxy dead from here -> hist overlay

    // zero the 4096-bin histogram
#pragma unroll
    for (int i = 0; i < 16; i++) u_.hist[tid + i * 256] = 0u;
    __syncthreads();

    // stage 3: vertical 7-tap gaussian + Harris + warp-aggregated smem hist
    {
        const int tx = tid & 31, r0q = (tid >> 5) * 4;
        u64 v01[10]; float v2[10];
#pragma unroll
        for (int i = 0; i < 10; i++) {
            v01[i] = sh01[r0q + i][tx];
            v2[i]  = sh2 [r0q + i][tx];
        }
#pragma unroll
        for (int j = 0; j < 4; j++) {
            u64 a01 = pk2(0.0f, 0.0f);
            float a2 = 0.0f;
#pragma unroll
            for (int k = 0; k < 7; k++) {
                a01 = fma2(w2[k], v01[j + k], a01);
                a2  = fmaf(w[k], v2[j + k], a2);
            }
            float a0, a1; upk2(a01, a0, a1);
            float tr = a0 + a1;
            float R  = (a0 * a1 - a2 * a2) - 0.05f * tr * tr;
            g_R[(by + r0q + j) * IMN + (bx + tx)] = R;

            // warp-aggregated histogram add (lanes with same bin elect leader)
            unsigned bin  = f2u(R) >> 20;
            unsigned mask = __match_any_sync(0xFFFFFFFFu, bin);
            if ((mask & ((1u << tx) - 1u)) == 0u)          // lowest lane in group
                atomicAdd(&u_.hist[bin], (unsigned)__popc(mask));
        }
    }
    __syncthreads();

    // merge: skip-zero, 8-way replicated to spread hot-bin atomics
    {
        unsigned* dst = &g_hist12[((blockIdx.x ^ blockIdx.y) & 7) * 4096];
#pragma unroll
        for (int i = 0; i < 16; i++) {
            int b = tid + i * 256;
            unsigned c = u_.hist[b];
            if (c) atomicAdd(&dst[b], c);
        }
    }
}

// ---------------- select over 4096 bins x 8 replicas (single block) --------
__global__ __launch_bounds__(1024) void k_sel12() {
    const int tid = threadIdx.x;
    const unsigned rank = MED_RANK;

    unsigned cnt[4];
    unsigned s = 0u;
#pragma unroll
    for (int j = 0; j < 4; j++) {
        int b = tid * 4 + j;
        unsigned c = 0u;
#pragma unroll
        for (int rep = 0; rep < 8; rep++) c += g_hist12[rep * 4096 + b];
        cnt[j] = c;
        s += c;
    }

    unsigned v = s;
    const int lane = tid & 31, wid = tid >> 5;
#pragma unroll
    for (int o = 1; o < 32; o <<= 1) {
        unsigned t = __shfl_up_sync(0xFFFFFFFFu, v, o);
        if (lane >= o) v += t;
    }
    __shared__ unsigned wsum[32];
    if (lane == 31) wsum[wid] = v;
    __syncthreads();
    if (tid < 32) {
        unsigned t = wsum[tid];
#pragma unroll
        for (int o = 1; o < 32; o <<= 1) {
            unsigned q = __shfl_up_sync(0xFFFFFFFFu, t, o);
            if (tid >= o) t += q;
        }
        wsum[tid] = t;
    }
    __syncthreads();
    unsigned incl   = v + (wid ? wsum[wid - 1] : 0u);
    unsigned before = incl - s;

    if (s > 0u && rank >= before && rank < incl) {
        unsigned run = before;
#pragma unroll
        for (int j = 0; j < 4; j++) {
            if (rank < run + cnt[j]) {
                g_prefix = (unsigned)(tid * 4 + j);   // 12-bit bin value
                g_rank   = rank - run;
                break;
            }
            run += cnt[j];
        }
    }
}

// ---------------- pass 2: 2^20-bin global histogram over matching elems ----
// Also zeroes g_hist12 for the next graph replay (k_sel12 already consumed it).
__global__ __launch_bounds__(256) void k_hist20() {
    int gt = blockIdx.x * 256 + threadIdx.x;
    if (gt < 8 * 4096) g_hist12[gt] = 0u;

    const unsigned pref = g_prefix;
    const float4* R4 = (const float4*)g_R;
    const int n4 = NPIX / 4;
    const int stride = gridDim.x * blockDim.x;
    for (int i = gt; i < n4; i += stride) {
        float4 v = R4[i];
        unsigned u;
        u = f2u(v.x); if ((u >> 20) == pref) atomicAdd(&g_hist20[u & 0xFFFFFu], 1u);
        u = f2u(v.y); if ((u >> 20) == pref) atomicAdd(&g_hist20[u & 0xFFFFFu], 1u);
        u = f2u(v.z); if ((u >> 20) == pref) atomicAdd(&g_hist20[u & 0xFFFFFu], 1u);
        u = f2u(v.w); if ((u >> 20) == pref) atomicAdd(&g_hist20[u & 0xFFFFFu], 1u);
    }
}

// ---------------- 20-bit select, level 1: 1024 chunk sums of 1024 bins -----
__global__ __launch_bounds__(256) void k_sum20() {
    const int tid = threadIdx.x;
    unsigned base = blockIdx.x << 10;
    unsigned s = 0u;
#pragma unroll
    for (int j = 0; j < 4; j++) s += g_hist20[base + tid + j * 256];

#pragma unroll
    for (int o = 16; o > 0; o >>= 1) s += __shfl_down_sync(0xFFFFFFFFu, s, o);
    __shared__ unsigned ws[8];
    if ((tid & 31) == 0) ws[tid >> 5] = s;
    __syncthreads();
    if (tid == 0) {
        unsigned t = 0u;
#pragma unroll
        for (int j = 0; j < 8; j++) t += ws[j];
        g_chunk[blockIdx.x] = t;
    }
}

// ---------------- 20-bit select, level 2 (single block, 1024 threads) ------
__global__ __launch_bounds__(1024) void k_sel20() {
    const int tid = threadIdx.x;
    const int lane = tid & 31, wid = tid >> 5;
    const unsigned rank = g_rank;
    __shared__ unsigned wsum[32];
    __shared__ unsigned sh_chunk, sh_rank2;

    // phase 1: scan 1024 chunk sums, locate chunk
    unsigned s = g_chunk[tid];
    unsigned v = s;
#pragma unroll
    for (int o = 1; o < 32; o <<= 1) {
        unsigned t = __shfl_up_sync(0xFFFFFFFFu, v, o);
        if (lane >= o) v += t;
    }
    if (lane == 31) wsum[wid] = v;
    __syncthreads();
    if (tid < 32) {
        unsigned t = wsum[tid];
#pragma unroll
        for (int o = 1; o < 32; o <<= 1) {
            unsigned q = __shfl_up_sync(0xFFFFFFFFu, t, o);
            if (tid >= o) t += q;
        }
        wsum[tid] = t;
    }
    __syncthreads();
    unsigned incl   = v + (wid ? wsum[wid - 1] : 0u);
    unsigned before = incl - s;
    if (s > 0u && rank >= before && rank < incl) {
        sh_chunk = (unsigned)tid;
        sh_rank2 = rank - before;
    }
    __syncthreads();

    // phase 2: scan the chosen 1024-bin chunk (1 bin/thread)
    const unsigned chunk = sh_chunk;
    const unsigned r2 = sh_rank2;
    const unsigned base = chunk << 10;
    s = g_hist20[base + tid];
    v = s;
    __syncthreads();   // wsum reuse
#pragma unroll
    for (int o = 1; o < 32; o <<= 1) {
        unsigned t = __shfl_up_sync(0xFFFFFFFFu, v, o);
        if (lane >= o) v += t;
    }
    if (lane == 31) wsum[wid] = v;
    __syncthreads();
    if (tid < 32) {
        unsigned t = wsum[tid];
#pragma unroll
        for (int o = 1; o < 32; o <<= 1) {
            unsigned q = __shfl_up_sync(0xFFFFFFFFu, t, o);
            if (tid >= o) t += q;
        }
        wsum[tid] = t;
    }
    __syncthreads();
    incl   = v + (wid ? wsum[wid - 1] : 0u);
    before = incl - s;
    if (s > 0u && r2 >= before && r2 < incl) {
        g_med = u2f((g_prefix << 20) | (base + tid));
    }
}

// ---------------- fused threshold + 7x7 NMS maxpool + mask ----------------
// 64x32 tile, vertical max first. Interior fast path (no guards, 97% of
// blocks). Also zeroes g_hist20 for next replay.
__global__ __launch_bounds__(256) void k_nms(float* __restrict__ out) {
    __shared__ float sr[38][71];   // thresholded R: rows by-3..by+34, cols bx-3..bx+66
    __shared__ float vm[32][71];   // vertical 7-max
    const int tid = threadIdx.x;
    const int bx = blockIdx.x * 64, by = blockIdx.y * 32;
    const float med = g_med;
    const bool interior = (blockIdx.x != 0) & (blockIdx.x != 63) &
                          (blockIdx.y != 0) & (blockIdx.y != 127);

    // zero 128 entries of g_hist20 per block (8192 blocks x 128 = 2^20)
    {
        int bid = blockIdx.y * gridDim.x + blockIdx.x;
        if (tid < 128) g_hist20[bid * 128 + tid] = 0u;
    }

    if (interior) {
        const float* Rb = g_R + (by - 3) * IMN + (bx - 3);
        for (int i = tid; i < 38 * 70; i += 256) {
            int r = i / 70, c = i % 70;
            float q = Rb[r * IMN + c];
            sr[r][c] = (q < med) ? 0.0f : q;
        }
    } else {
        for (int i = tid; i < 38 * 70; i += 256) {
            int r = i / 70, c = i % 70;
            int gy = by - 3 + r, gx = bx - 3 + c;
            float v = -INFINITY;
            if ((unsigned)gy < IMN && (unsigned)gx < IMN) {
                float q = g_R[gy * IMN + gx];
                v = (q < med) ? 0.0f : q;
            }
            sr[r][c] = v;
        }
    }
    __syncthreads();

    // vertical 7-max: 70 cols x 4 row-groups (280 tasks)
    for (int t = tid; t < 280; t += 256) {
        int c  = t % 70;
        int r0 = (t / 70) * 8;
        float wv[14];
#pragma unroll
        for (int i = 0; i < 14; i++) wv[i] = sr[r0 + i][c];
        float m1[13], m2[11];
#pragma unroll
        for (int i = 0; i < 13; i++) m1[i] = fmaxf(wv[i], wv[i + 1]);
#pragma unroll
        for (int i = 0; i < 11; i++) m2[i] = fmaxf(m1[i], m1[i + 2]);
#pragma unroll
        for (int j = 0; j < 8; j++) vm[r0 + j][c] = fmaxf(m2[j], m2[j + 3]);
    }
    __syncthreads();

    // horizontal 7-max + mask (256 tasks exact)
    {
        const int r  = tid & 31;
        const int cb = (tid >> 5) * 8;
        float wv[14];
#pragma unroll
        for (int i = 0; i < 14; i++) wv[i] = vm[r][cb + i];
        float m1[13], m2[11];
#pragma unroll
        for (int i = 0; i < 13; i++) m1[i] = fmaxf(wv[i], wv[i + 1]);
#pragma unroll
        for (int i = 0; i < 11; i++) m2[i] = fmaxf(m1[i], m1[i + 2]);
        float o[8];
#pragma unroll
        for (int j = 0; j < 8; j++) {
            float m   = fmaxf(m2[j], m2[j + 3]);
            float ctr = sr[r + 3][cb + j + 3];
            o[j] = (ctr == m) ? ctr : 0.0f;
        }
        float4* dst = (float4*)&out[(by + r) * IMN + bx + cb];
        dst[0] = make_float4(o[0], o[1], o[2], o[3]);
        dst[1] = make_float4(o[4], o[5], o[6], o[7]);
    }
}

// ---------------- launch ----------------
extern "C" void kernel_launch(void* const* d_in, const int* in_sizes, int n_in,
                              void* d_out, int out_size) {
    const float* x  = (const float*)d_in[0];
    const float* gk = (const float*)d_in[1];
    float* out = (float*)d_out;

    dim3 gridR(IMN / 32, IMN / 32);
    dim3 gridN(IMN / 64, IMN / 32);

    k_R<<<gridR, 256>>>(x, gk);          // fused: R + 12-bit hist (warp-agg)
    k_sel12<<<1, 1024>>>();
    k_hist20<<<1184, 256>>>();
    k_sum20<<<1024, 256>>>();
    k_sel20<<<1, 1024>>>();
    k_nms<<<gridN, 256>>>(out);
}

// round 16
// speedup vs baseline: 1.0699x; 1.0699x over previous
#include <cuda_runtime.h>
#include <math.h>

#define IMN 4096
#define NPIX (IMN*IMN)
#define MED_RANK 8388607u   /* (NPIX-1)/2 */

typedef unsigned long long u64;

// ---------------- packed f32x2 helpers (Blackwell) ----------------
__device__ __forceinline__ u64 pk2(float lo, float hi) {
    u64 d; asm("mov.b64 %0, {%1, %2};" : "=l"(d) : "f"(lo), "f"(hi)); return d;
}
__device__ __forceinline__ void upk2(u64 v, float& lo, float& hi) {
    asm("mov.b64 {%0, %1}, %2;" : "=f"(lo), "=f"(hi) : "l"(v));
}
__device__ __forceinline__ u64 mul2(u64 a, u64 b) {
    u64 d; asm("mul.rn.f32x2 %0, %1, %2;" : "=l"(d) : "l"(a), "l"(b)); return d;
}
__device__ __forceinline__ u64 fma2(u64 a, u64 b, u64 c) {
    u64 d; asm("fma.rn.f32x2 %0, %1, %2, %3;" : "=l"(d) : "l"(a), "l"(b), "l"(c)); return d;
}

// ---------------- device scratch (no allocations allowed) ----------------
__device__ float    g_R[NPIX];            // Harris response
__device__ unsigned g_hist13[8192];       // pass-1 histogram (top 13 bits)
__device__ unsigned g_hist19[1 << 19];    // pass-2 histogram (low 19 bits)
__device__ unsigned g_chunk[512];         // chunk sums for 19-bit select
__device__ unsigned g_prefix;             // selected top-13-bit bin
__device__ unsigned g_rank;               // remaining rank
__device__ float    g_med;                // selected median value

// monotonic float<->uint order transform
__device__ __forceinline__ unsigned f2u(float f) {
    unsigned u = __float_as_uint(f);
    return (u & 0x80000000u) ? ~u : (u | 0x80000000u);
}
__device__ __forceinline__ float u2f(unsigned u) {
    return (u & 0x80000000u) ? __uint_as_float(u & 0x7fffffffu)
                             : __uint_as_float(~u);
}

// ---------------- fused Sobel + products + 7x7 Gaussian -> R ----------------
// 32x32 output tile, halo 4. 256 threads, 6 blocks/SM (round-13 proven best).
// Padded smem kills the c-bound selects; interior fast path kills image-
// boundary guards for 97% of blocks. Per-output FP op sequence identical to
// round-8..13 => bit-exact R.
__global__ __launch_bounds__(256, 6) void k_R(const float* __restrict__ x,
                                              const float* __restrict__ gk) {
    __shared__ float sx  [40][45];    // cols 40..44 padding (garbage ok)
    __shared__ u64   sIxy[38][43];    // packed (Ix,Iy); cols 38..42 padding
    __shared__ u64   sh01[38][33];    // packed (blur(Ix^2), blur(Iy^2))
    __shared__ float sh2 [38][33];    // blur(Ix*Iy)

    const int tid = threadIdx.x;
    const int bx = blockIdx.x * 32, by = blockIdx.y * 32;
    const bool interior = (blockIdx.x != 0) & (blockIdx.x != 127) &
                          (blockIdx.y != 0) & (blockIdx.y != 127);

    // 1D gaussian factors from provided 2D kernel: w[k] = g2[3][k]/sqrt(g2[3][3])
    float winv = rsqrtf(gk[24]);
    float w[7]; u64 w2[7];
#pragma unroll
    for (int k = 0; k < 7; k++) { w[k] = gk[21 + k] * winv; w2[k] = pk2(w[k], w[k]); }

    // stage 0: load x tile (interior: unguarded)
    if (interior) {
        const float* xb = x + (by - 4) * IMN + (bx - 4);
#pragma unroll
        for (int i = tid; i < 40 * 40; i += 256) {
            int r = i / 40, c = i % 40;
            sx[r][c] = xb[r * IMN + c];
        }
    } else {
        for (int i = tid; i < 40 * 40; i += 256) {
            int r = i / 40, c = i % 40;
            int gy = by - 4 + r, gx = bx - 4 + c;
            float v = 0.0f;
            if ((unsigned)gy < IMN && (unsigned)gx < IMN) v = x[gy * IMN + gx];
            sx[r][c] = v;
        }
    }
    __syncthreads();

    // stage 1: Sobel; 7 consecutive cols per task (38 rows x 6 groups = 228 tasks)
    if (tid < 228) {
        int r  = tid % 38;
        int cb = (tid / 38) * 7;          // 0,7,...,35
        float r0[9], r1[9], r2[9];
#pragma unroll
        for (int j = 0; j < 9; j++) {     // unguarded: sx padded to 45 cols
            r0[j] = sx[r    ][cb + j];
            r1[j] = sx[r + 1][cb + j];
            r2[j] = sx[r + 2][cb + j];
        }
        if (interior) {
#pragma unroll
            for (int j = 0; j < 7; j++) {
                int c = cb + j;
                if (c < 38) {
                    float ix = (r0[j+2] - r0[j]) + 2.0f*(r1[j+2] - r1[j]) + (r2[j+2] - r2[j]);
                    float iy = (r2[j] + 2.0f*r2[j+1] + r2[j+2]) - (r0[j] + 2.0f*r0[j+1] + r0[j+2]);
                    sIxy[r][c] = pk2(ix, iy);
                }
            }
        } else {
            int gy = by - 3 + r;
            bool rowok = (unsigned)gy < IMN;
#pragma unroll
            for (int j = 0; j < 7; j++) {
                int c = cb + j;
                if (c < 38) {
                    float ix = 0.0f, iy = 0.0f;
                    int gx = bx - 3 + c;
                    if (rowok && (unsigned)gx < IMN) {
                        ix = (r0[j+2] - r0[j]) + 2.0f*(r1[j+2] - r1[j]) + (r2[j+2] - r2[j]);
                        iy = (r2[j] + 2.0f*r2[j+1] + r2[j+2]) - (r0[j] + 2.0f*r0[j+1] + r0[j+2]);
                    }
                    sIxy[r][c] = pk2(ix, iy);
                }
            }
        }
    }
    __syncthreads();

    // stage 2: horizontal 7-tap gaussian; 6 cols per task (38 x 6 = 228 tasks)
    if (tid < 228) {
        int r  = tid % 38;
        int cb = (tid / 38) * 6;          // 0,6,...,30
        u64 p01[12]; float p2[12];
#pragma unroll
        for (int i = 0; i < 12; i++) {    // unguarded: sIxy padded to 43 cols;
            u64 dp = sIxy[r][cb + i];     // garbage only feeds skipped outputs
            float ax, ay; upk2(dp, ax, ay);
            p01[i] = mul2(dp, dp);        // (Ix*Ix, Iy*Iy), rn each lane
            p2[i]  = ax * ay;
        }
#pragma unroll
        for (int j = 0; j < 6; j++) {
            int c = cb + j;
            if (c < 32) {
                u64 a01 = pk2(0.0f, 0.0f);
                float a2 = 0.0f;
#pragma unroll
                for (int k = 0; k < 7; k++) {
                    a01 = fma2(w2[k], p01[j + k], a01);
                    a2  = fmaf(w[k], p2[j + k], a2);
                }
                sh01[r][c] = a01;
                sh2 [r][c] = a2;
            }
        }
    }
    __syncthreads();

    // stage 3: vertical 7-tap gaussian + Harris (256 tasks exact)
    {
        const int tx = tid & 31, r0 = (tid >> 5) * 4;
        u64 v01[10]; float v2[10];
#pragma unroll
        for (int i = 0; i < 10; i++) {
            v01[i] = sh01[r0 + i][tx];
            v2[i]  = sh2 [r0 + i][tx];
        }
#pragma unroll
        for (int j = 0; j < 4; j++) {
            u64 a01 = pk2(0.0f, 0.0f);
            float a2 = 0.0f;
#pragma unroll
            for (int k = 0; k < 7; k++) {
                a01 = fma2(w2[k], v01[j + k], a01);
                a2  = fmaf(w[k], v2[j + k], a2);
            }
            float a0, a1; upk2(a01, a0, a1);
            float tr = a0 + a1;
            float R  = (a0 * a1 - a2 * a2) - 0.05f * tr * tr;
            g_R[(by + r0 + j) * IMN + (bx + tx)] = R;
        }
    }
}

// ---------------- pass 1: 8192-bin smem-privatized histogram ----------------
__global__ __launch_bounds__(256) void k_hist1() {
    __shared__ unsigned h[8192];
    for (int b = threadIdx.x; b < 8192; b += 256) h[b] = 0u;
    __syncthreads();

    const float4* R4 = (const float4*)g_R;
    const int n4 = NPIX / 4;
    const int stride = gridDim.x * blockDim.x;
    for (int i = blockIdx.x * blockDim.x + threadIdx.x; i < n4; i += stride) {
        float4 v = R4[i];
        atomicAdd(&h[f2u(v.x) >> 19], 1u);
        atomicAdd(&h[f2u(v.y) >> 19], 1u);
        atomicAdd(&h[f2u(v.z) >> 19], 1u);
        atomicAdd(&h[f2u(v.w) >> 19], 1u);
    }
    __syncthreads();
    for (int b = threadIdx.x; b < 8192; b += 256) {
        unsigned c = h[b];
        if (c) atomicAdd(&g_hist13[b], c);
    }
}

// ---------------- parallel select over 8192 bins (single block, 1024 thr) --
__global__ __launch_bounds__(1024) void k_sel1() {
    const int tid = threadIdx.x;
    const unsigned rank = MED_RANK;

    unsigned cnt[8];
    unsigned s = 0u;
#pragma unroll
    for (int j = 0; j < 8; j++) { cnt[j] = g_hist13[tid * 8 + j]; s += cnt[j]; }

    unsigned v = s;
    const int lane = tid & 31, wid = tid >> 5;
#pragma unroll
    for (int o = 1; o < 32; o <<= 1) {
        unsigned t = __shfl_up_sync(0xFFFFFFFFu, v, o);
        if (lane >= o) v += t;
    }
    __shared__ unsigned wsum[32];
    if (lane == 31) wsum[wid] = v;
    __syncthreads();
    if (tid < 32) {
        unsigned t = wsum[tid];
#pragma unroll
        for (int o = 1; o < 32; o <<= 1) {
            unsigned q = __shfl_up_sync(0xFFFFFFFFu, t, o);
            if (tid >= o) t += q;
        }
        wsum[tid] = t;
    }
    __syncthreads();
    unsigned incl   = v + (wid ? wsum[wid - 1] : 0u);
    unsigned before = incl - s;

    if (s > 0u && rank >= before && rank < incl) {
        unsigned run = before;
#pragma unroll
        for (int j = 0; j < 8; j++) {
            if (rank < run + cnt[j]) {
                g_prefix = (unsigned)(tid * 8 + j);   // 13-bit bin value
                g_rank   = rank - run;
                break;
            }
            run += cnt[j];
        }
    }
}

// ---------------- pass 2: 2^19-bin global histogram over matching elems ----
// Also zeroes g_hist13 for the next graph replay (k_sel1 already consumed it).
__global__ __launch_bounds__(256) void k_hist19() {
    int gt = blockIdx.x * 256 + threadIdx.x;
    if (gt < 8192) g_hist13[gt] = 0u;

    const unsigned pref = g_prefix;
    const float4* R4 = (const float4*)g_R;
    const int n4 = NPIX / 4;
    const int stride = gridDim.x * blockDim.x;
    for (int i = gt; i < n4; i += stride) {
        float4 v = R4[i];
        unsigned u;
        u = f2u(v.x); if ((u >> 19) == pref) atomicAdd(&g_hist19[u & 0x7FFFFu], 1u);
        u = f2u(v.y); if ((u >> 19) == pref) atomicAdd(&g_hist19[u & 0x7FFFFu], 1u);
        u = f2u(v.z); if ((u >> 19) == pref) atomicAdd(&g_hist19[u & 0x7FFFFu], 1u);
        u = f2u(v.w); if ((u >> 19) == pref) atomicAdd(&g_hist19[u & 0x7FFFFu], 1u);
    }
}

// ---------------- 19-bit select, level 1: 512 chunk sums of 1024 bins ------
__global__ __launch_bounds__(256) void k_sum19() {
    const int tid = threadIdx.x;
    unsigned base = blockIdx.x << 10;
    unsigned s = 0u;
#pragma unroll
    for (int j = 0; j < 4; j++) s += g_hist19[base + tid + j * 256];

#pragma unroll
    for (int o = 16; o > 0; o >>= 1) s += __shfl_down_sync(0xFFFFFFFFu, s, o);
    __shared__ unsigned ws[8];
    if ((tid & 31) == 0) ws[tid >> 5] = s;
    __syncthreads();
    if (tid == 0) {
        unsigned t = 0u;
#pragma unroll
        for (int j = 0; j < 8; j++) t += ws[j];
        g_chunk[blockIdx.x] = t;
    }
}

// ---------------- 19-bit select, level 2 (single block, 512 threads) -------
__global__ __launch_bounds__(512) void k_sel19() {
    const int tid = threadIdx.x;
    const int lane = tid & 31, wid = tid >> 5;
    const unsigned rank = g_rank;
    __shared__ unsigned wsum[16];
    __shared__ unsigned sh_chunk, sh_rank2;

    // phase 1: scan 512 chunk sums, locate chunk
    unsigned s = g_chunk[tid];
    unsigned v = s;
#pragma unroll
    for (int o = 1; o < 32; o <<= 1) {
        unsigned t = __shfl_up_sync(0xFFFFFFFFu, v, o);
        if (lane >= o) v += t;
    }
    if (lane == 31) wsum[wid] = v;
    __syncthreads();
    if (tid < 16) {
        unsigned t = wsum[tid];
#pragma unroll
        for (int o = 1; o < 16; o <<= 1) {
            unsigned q = __shfl_up_sync(0xFFFFu, t, o);
            if (tid >= o) t += q;
        }
        wsum[tid] = t;
    }
    __syncthreads();
    unsigned incl   = v + (wid ? wsum[wid - 1] : 0u);
    unsigned before = incl - s;
    if (s > 0u && rank >= before && rank < incl) {
        sh_chunk = (unsigned)tid;
        sh_rank2 = rank - before;
    }
    __syncthreads();

    // phase 2: scan the chosen 1024-bin chunk (2 bins/thread)
    const unsigned chunk = sh_chunk;
    const unsigned r2 = sh_rank2;
    const unsigned base = chunk << 10;
    unsigned c0 = g_hist19[base + 2 * tid];
    unsigned c1 = g_hist19[base + 2 * tid + 1];
    s = c0 + c1;
    v = s;
    __syncthreads();   // wsum reuse
#pragma unroll
    for (int o = 1; o < 32; o <<= 1) {
        unsigned t = __shfl_up_sync(0xFFFFFFFFu, v, o);
        if (lane >= o) v += t;
    }
    if (lane == 31) wsum[wid] = v;
    __syncthreads();
    if (tid < 16) {
        unsigned t = wsum[tid];
#pragma unroll
        for (int o = 1; o < 16; o <<= 1) {
            unsigned q = __shfl_up_sync(0xFFFFu, t, o);
            if (tid >= o) t += q;
        }
        wsum[tid] = t;
    }
    __syncthreads();
    incl   = v + (wid ? wsum[wid - 1] : 0u);
    before = incl - s;
    if (s > 0u && r2 >= before && r2 < incl) {
        unsigned bin19 = base + 2 * tid + ((r2 < before + c0) ? 0u : 1u);
        g_med = u2f((g_prefix << 19) | bin19);
    }
}

// ---------------- fused threshold + 7x7 NMS maxpool + mask ----------------
// 64x32 tile, vertical max first. Interior fast path (no guards, 97% of
// blocks; exact arithmetic). Also zeroes g_hist19 for next replay.
__global__ __launch_bounds__(256) void k_nms(float* __restrict__ out) {
    __shared__ float sr[38][71];   // thresholded R: rows by-3..by+34, cols bx-3..bx+66
    __shared__ float vm[32][71];   // vertical 7-max
    const int tid = threadIdx.x;
    const int bx = blockIdx.x * 64, by = blockIdx.y * 32;
    const float med = g_med;
    const bool interior = (blockIdx.x != 0) & (blockIdx.x != 63) &
                          (blockIdx.y != 0) & (blockIdx.y != 127);

    // zero 64 entries of g_hist19 per block (8192 blocks x 64 = 2^19)
    {
        int bid = blockIdx.y * gridDim.x + blockIdx.x;
        if (tid < 64) g_hist19[bid * 64 + tid] = 0u;
    }

    if (interior) {
        const float* Rb = g_R + (by - 3) * IMN + (bx - 3);
        for (int i = tid; i < 38 * 70; i += 256) {
            int r = i / 70, c = i % 70;
            float q = Rb[r * IMN + c];
            sr[r][c] = (q < med) ? 0.0f : q;
        }
    } else {
        for (int i = tid; i < 38 * 70; i += 256) {
            int r = i / 70, c = i % 70;
            int gy = by - 3 + r, gx = bx - 3 + c;
            float v = -INFINITY;
            if ((unsigned)gy < IMN && (unsigned)gx < IMN) {
                float q = g_R[gy * IMN + gx];
                v = (q < med) ? 0.0f : q;
            }
            sr[r][c] = v;
        }
    }
    __syncthreads();

    // vertical 7-max: 70 cols x 4 row-groups (280 tasks)
    for (int t = tid; t < 280; t += 256) {
        int c  = t % 70;
        int r0 = (t / 70) * 8;
        float wv[14];
#pragma unroll
        for (int i = 0; i < 14; i++) wv[i] = sr[r0 + i][c];
        float m1[13], m2[11];
#pragma unroll
        for (int i = 0; i < 13; i++) m1[i] = fmaxf(wv[i], wv[i + 1]);
#pragma unroll
        for (int i = 0; i < 11; i++) m2[i] = fmaxf(m1[i], m1[i + 2]);
#pragma unroll
        for (int j = 0; j < 8; j++) vm[r0 + j][c] = fmaxf(m2[j], m2[j + 3]);
    }
    __syncthreads();

    // horizontal 7-max + mask (256 tasks exact)
    {
        const int r  = tid & 31;
        const int cb = (tid >> 5) * 8;
        float wv[14];
#pragma unroll
        for (int i = 0; i < 14; i++) wv[i] = vm[r][cb + i];
        float m1[13], m2[11];
#pragma unroll
        for (int i = 0; i < 13; i++) m1[i] = fmaxf(wv[i], wv[i + 1]);
#pragma unroll
        for (int i = 0; i < 11; i++) m2[i] = fmaxf(m1[i], m1[i + 2]);
        float o[8];
#pragma unroll
        for (int j = 0; j < 8; j++) {
            float m   = fmaxf(m2[j], m2[j + 3]);
            float ctr = sr[r + 3][cb + j + 3];
            o[j] = (ctr == m) ? ctr : 0.0f;
        }
        float4* dst = (float4*)&out[(by + r) * IMN + bx + cb];
        dst[0] = make_float4(o[0], o[1], o[2], o[3]);
        dst[1] = make_float4(o[4], o[5], o[6], o[7]);
    }
}

// ---------------- launch ----------------
extern "C" void kernel_launch(void* const* d_in, const int* in_sizes, int n_in,
                              void* d_out, int out_size) {
    const float* x  = (const float*)d_in[0];
    const float* gk = (const float*)d_in[1];
    float* out = (float*)d_out;

    dim3 gridR(IMN / 32, IMN / 32);
    dim3 gridN(IMN / 64, IMN / 32);

    k_R<<<gridR, 256>>>(x, gk);
    k_hist1<<<1184, 256>>>();
    k_sel1<<<1, 1024>>>();
    k_hist19<<<1184, 256>>>();
    k_sum19<<<512, 256>>>();
    k_sel19<<<1, 512>>>();
    k_nms<<<gridN, 256>>>(out);
}